// round 15
// baseline (speedup 1.0000x reference)
#include <cuda_runtime.h>
#include <cuda_bf16.h>
#include <cuda_fp16.h>
#include <cstdint>

#define NN   50000
#define NE   800000
#define FIN  128
#define HID  256
#define NG   128
#define NBLK 196   // ceil(NN/256)

// ---------------- device scratch --------------------------------------------
__device__ __align__(16) __nv_bfloat16 g_axh[NN * FIN];   // split-bf16 spmm(x)
__device__ __align__(16) __nv_bfloat16 g_axl[NN * FIN];
__device__ __align__(16) __nv_bfloat16 g_h1h[NN * HID];   // split-bf16 h1
__device__ __align__(16) __nv_bfloat16 g_h1l[NN * HID];
__device__ __align__(16) __half       g_t2h[NN * HID];    // t2 = h1@W2, fp16
__device__ __align__(16) __half       g_x16[NN * FIN];    // x in fp16
__device__ float4 g_h2[NN * HID / 4];                     // relu(spmm(t2)+b2)
__device__ __align__(16) __nv_bfloat16 g_W1th[HID * FIN]; // W1^T split-bf16
__device__ __align__(16) __nv_bfloat16 g_W1tl[HID * FIN];
__device__ __align__(16) __nv_bfloat16 g_W2th[HID * HID];
__device__ __align__(16) __nv_bfloat16 g_W2tl[HID * HID];
__device__ int    g_deg[NN];
__device__ int    g_rp[NN + 1];
__device__ int    g_cursor[NN];
__device__ __align__(16) int2 g_edge[NE];                 // {src, w bits}
__device__ float  g_pool[NG * HID];
__device__ int    g_bsum[256];
__device__ int    g_bpre[256];

// ---------------- helpers ---------------------------------------------------
__device__ __forceinline__ uint32_t pack2(__nv_bfloat16 lo, __nv_bfloat16 hi) {
    __nv_bfloat162 t = __halves2bfloat162(lo, hi);
    return *(uint32_t*)&t;
}
__device__ __forceinline__ void splitf(float a, __nv_bfloat16& h, __nv_bfloat16& l) {
    h = __float2bfloat16_rn(a);
    l = __float2bfloat16_rn(a - __bfloat162float(h));
}
__device__ __forceinline__ void cp16(uint32_t dst, const void* src, bool p) {
    asm volatile("cp.async.cg.shared.global [%0], [%1], 16, %2;"
                 :: "r"(dst), "l"(src), "r"(p ? 16 : 0));
}

// ---------------- CSR build -------------------------------------------------
__global__ void zero_kernel() {
    int i = blockIdx.x * blockDim.x + threadIdx.x;
    if (i < NN) g_deg[i] = 0;
    if (i < NG * HID) g_pool[i] = 0.0f;
}

__global__ void hist_kernel(const int* __restrict__ dst) {
    int e = blockIdx.x * blockDim.x + threadIdx.x;
    if (e < NE) atomicAdd(&g_deg[dst[e]], 1);
}

__global__ void __launch_bounds__(256) scan_pre_kernel() {
    __shared__ int s[256];
    int i = blockIdx.x * 256 + threadIdx.x;
    int v = (i < NN) ? g_deg[i] : 0;
    s[threadIdx.x] = v;
    __syncthreads();
    for (int off = 128; off > 0; off >>= 1) {
        if (threadIdx.x < off) s[threadIdx.x] += s[threadIdx.x + off];
        __syncthreads();
    }
    if (threadIdx.x == 0) g_bsum[blockIdx.x] = s[0];
}

__global__ void __launch_bounds__(256) scan_mid_kernel() {
    __shared__ int s[256];
    int t = threadIdx.x;
    int v = (t < NBLK) ? g_bsum[t] : 0;
    s[t] = v;
    __syncthreads();
    for (int off = 1; off < 256; off <<= 1) {
        int add = (t >= off) ? s[t - off] : 0;
        __syncthreads();
        s[t] += add;
        __syncthreads();
    }
    g_bpre[t] = s[t] - v;
    if (t == 255) g_rp[NN] = s[255];
}

__global__ void __launch_bounds__(256) scan_post_kernel() {
    __shared__ int wsum[8];
    int t = threadIdx.x, lane = t & 31, w = t >> 5;
    int i = blockIdx.x * 256 + t;
    int v = (i < NN) ? g_deg[i] : 0;
    int incl = v;
    #pragma unroll
    for (int o = 1; o < 32; o <<= 1) {
        int x = __shfl_up_sync(0xffffffffu, incl, o);
        if (lane >= o) incl += x;
    }
    if (lane == 31) wsum[w] = incl;
    __syncthreads();
    if (w == 0 && lane < 8) {
        int x = wsum[lane];
        #pragma unroll
        for (int o = 1; o < 8; o <<= 1) {
            int y = __shfl_up_sync(0xffu, x, o);
            if (lane >= o) x += y;
        }
        wsum[lane] = x;
    }
    __syncthreads();
    int base = g_bpre[blockIdx.x] + ((w > 0) ? wsum[w - 1] : 0);
    int excl = base + incl - v;
    if (i < NN) { g_rp[i] = excl; g_cursor[i] = excl; }
}

__global__ void fill_kernel(const int* __restrict__ src, const int* __restrict__ dst,
                            const float* __restrict__ ew) {
    int e = blockIdx.x * blockDim.x + threadIdx.x;
    if (e < NE) {
        int p = atomicAdd(&g_cursor[dst[e]], 1);
        g_edge[p] = make_int2(src[e], __float_as_int(ew[e]));
    }
}

// ---------------- x -> fp16 -------------------------------------------------
__global__ void __launch_bounds__(256) x2h_kernel(const float4* __restrict__ x4) {
    int i = blockIdx.x * blockDim.x + threadIdx.x;
    if (i < NN * FIN / 4) {
        float4 v = x4[i];
        __half2 a = __floats2half2_rn(v.x, v.y);
        __half2 b = __floats2half2_rn(v.z, v.w);
        ((uint2*)g_x16)[i] = make_uint2(*(uint32_t*)&a, *(uint32_t*)&b);
    }
}

// ---------------- weight transpose + split: W[K,N] -> (h,l)[N,K] ------------
__global__ void __launch_bounds__(256) transpose_split_kernel(
    const float* __restrict__ src, __nv_bfloat16* __restrict__ dh,
    __nv_bfloat16* __restrict__ dl, int K, int N)
{
    __shared__ float tile[32][33];
    int kb = blockIdx.x * 32, nb = blockIdx.y * 32;
    int tx = threadIdx.x & 31, ty = threadIdx.x >> 5;
    #pragma unroll
    for (int j = 0; j < 4; j++)
        tile[ty + 8 * j][tx] = src[(size_t)(kb + ty + 8 * j) * N + nb + tx];
    __syncthreads();
    #pragma unroll
    for (int j = 0; j < 4; j++) {
        float v = tile[tx][ty + 8 * j];
        __nv_bfloat16 h, l;
        splitf(v, h, l);
        size_t o = (size_t)(nb + ty + 8 * j) * K + kb + tx;
        dh[o] = h; dl[o] = l;
    }
}

// ---------------- SPMM 1: warp/node, 4-edge batched fp16 gather -------------
__device__ __forceinline__ void fma_h4(float4& acc, float w, uint2 u) {
    float2 f0 = __half22float2(*(__half2*)&u.x);
    float2 f1 = __half22float2(*(__half2*)&u.y);
    acc.x += w * f0.x; acc.y += w * f0.y;
    acc.z += w * f1.x; acc.w += w * f1.y;
}

__global__ void __launch_bounds__(256) spmm128_kernel() {
    int warp = (blockIdx.x * blockDim.x + threadIdx.x) >> 5;
    int lane = threadIdx.x & 31;
    if (warp >= NN) return;
    int e0 = g_rp[warp], e1 = g_rp[warp + 1];
    float4 acc0 = make_float4(0.f, 0.f, 0.f, 0.f);
    float4 acc1 = make_float4(0.f, 0.f, 0.f, 0.f);
    const __half* xb = g_x16;
    int e = e0;
    for (; e + 4 <= e1; e += 4) {
        int2 d0 = __ldg(&g_edge[e]);
        int2 d1 = __ldg(&g_edge[e + 1]);
        int2 d2 = __ldg(&g_edge[e + 2]);
        int2 d3 = __ldg(&g_edge[e + 3]);
        uint2 u0 = __ldg((const uint2*)(xb + (size_t)d0.x * FIN + lane * 4));
        uint2 u1 = __ldg((const uint2*)(xb + (size_t)d1.x * FIN + lane * 4));
        uint2 u2 = __ldg((const uint2*)(xb + (size_t)d2.x * FIN + lane * 4));
        uint2 u3 = __ldg((const uint2*)(xb + (size_t)d3.x * FIN + lane * 4));
        fma_h4(acc0, __int_as_float(d0.y), u0);
        fma_h4(acc1, __int_as_float(d1.y), u1);
        fma_h4(acc0, __int_as_float(d2.y), u2);
        fma_h4(acc1, __int_as_float(d3.y), u3);
    }
    for (; e < e1; e++) {
        int2 d = __ldg(&g_edge[e]);
        uint2 u = __ldg((const uint2*)(xb + (size_t)d.x * FIN + lane * 4));
        fma_h4(acc0, __int_as_float(d.y), u);
    }
    acc0.x += acc1.x; acc0.y += acc1.y; acc0.z += acc1.z; acc0.w += acc1.w;
    __nv_bfloat16 h0, l0, h1, l1, h2, l2, h3, l3;
    splitf(acc0.x, h0, l0); splitf(acc0.y, h1, l1);
    splitf(acc0.z, h2, l2); splitf(acc0.w, h3, l3);
    size_t o = (size_t)warp * FIN + lane * 4;
    *(uint2*)(g_axh + o) = make_uint2(pack2(h0, h1), pack2(h2, h3));
    *(uint2*)(g_axl + o) = make_uint2(pack2(l0, l1), pack2(l2, l3));
}

// ---------------- SPMM 2: warp/node, 4-edge batched fp16 gather -------------
__device__ __forceinline__ void fma_h8(float* a, float w, uint4 u) {
    float2 f0 = __half22float2(*(__half2*)&u.x);
    float2 f1 = __half22float2(*(__half2*)&u.y);
    float2 f2 = __half22float2(*(__half2*)&u.z);
    float2 f3 = __half22float2(*(__half2*)&u.w);
    a[0] += w * f0.x; a[1] += w * f0.y;
    a[2] += w * f1.x; a[3] += w * f1.y;
    a[4] += w * f2.x; a[5] += w * f2.y;
    a[6] += w * f3.x; a[7] += w * f3.y;
}

__global__ void __launch_bounds__(256) spmm256_kernel(const float* __restrict__ b2) {
    int warp = (blockIdx.x * blockDim.x + threadIdx.x) >> 5;
    int lane = threadIdx.x & 31;
    if (warp >= NN) return;
    int e0 = g_rp[warp], e1 = g_rp[warp + 1];
    float a0[8], a1[8];
    #pragma unroll
    for (int j = 0; j < 8; j++) { a0[j] = 0.f; a1[j] = 0.f; }
    const __half* tb = g_t2h;
    int e = e0;
    for (; e + 4 <= e1; e += 4) {
        int2 d0 = __ldg(&g_edge[e]);
        int2 d1 = __ldg(&g_edge[e + 1]);
        int2 d2 = __ldg(&g_edge[e + 2]);
        int2 d3 = __ldg(&g_edge[e + 3]);
        uint4 u0 = __ldg((const uint4*)(tb + (size_t)d0.x * HID + lane * 8));
        uint4 u1 = __ldg((const uint4*)(tb + (size_t)d1.x * HID + lane * 8));
        uint4 u2 = __ldg((const uint4*)(tb + (size_t)d2.x * HID + lane * 8));
        uint4 u3 = __ldg((const uint4*)(tb + (size_t)d3.x * HID + lane * 8));
        fma_h8(a0, __int_as_float(d0.y), u0);
        fma_h8(a1, __int_as_float(d1.y), u1);
        fma_h8(a0, __int_as_float(d2.y), u2);
        fma_h8(a1, __int_as_float(d3.y), u3);
    }
    for (; e < e1; e++) {
        int2 d = __ldg(&g_edge[e]);
        uint4 u = __ldg((const uint4*)(tb + (size_t)d.x * HID + lane * 8));
        fma_h8(a0, __int_as_float(d.y), u);
    }
    #pragma unroll
    for (int j = 0; j < 8; j++) a0[j] += a1[j];
    const float4* b4 = (const float4*)b2;
    float4 c0 = __ldg(&b4[lane * 2]);
    float4 c1 = __ldg(&b4[lane * 2 + 1]);
    float4 o0, o1;
    o0.x = fmaxf(a0[0] + c0.x, 0.f); o0.y = fmaxf(a0[1] + c0.y, 0.f);
    o0.z = fmaxf(a0[2] + c0.z, 0.f); o0.w = fmaxf(a0[3] + c0.w, 0.f);
    o1.x = fmaxf(a0[4] + c1.x, 0.f); o1.y = fmaxf(a0[5] + c1.y, 0.f);
    o1.z = fmaxf(a0[6] + c1.z, 0.f); o1.w = fmaxf(a0[7] + c1.w, 0.f);
    g_h2[warp * (HID / 4) + lane * 2]     = o0;
    g_h2[warp * (HID / 4) + lane * 2 + 1] = o1;
}

// ---------------- pipelined split-bf16 tensor-core GEMM ---------------------
#define GBM 128
#define GBN 128
#define GBK 32
#define APITCH 40
#define STG_HW (GBM * APITCH)
#define GEMM_SMEM (8 * STG_HW * 2)

#define LDSM4(R, addr)                                                         \
    asm volatile("ldmatrix.sync.aligned.m8n8.x4.shared.b16 {%0,%1,%2,%3}, [%4];" \
        : "=r"(R[0]), "=r"(R[1]), "=r"(R[2]), "=r"(R[3]) : "r"(addr))

#define MMA_BF16(C, A, B0, B1)                                                 \
    asm volatile(                                                              \
        "mma.sync.aligned.m16n8k16.row.col.f32.bf16.bf16.f32 "                 \
        "{%0,%1,%2,%3}, {%4,%5,%6,%7}, {%8,%9}, {%0,%1,%2,%3};"                \
        : "+f"(C[0]), "+f"(C[1]), "+f"(C[2]), "+f"(C[3])                       \
        : "r"(A[0]), "r"(A[1]), "r"(A[2]), "r"(A[3]), "r"(B0), "r"(B1))

__global__ void __launch_bounds__(256, 2) gemm_pipe_kernel(
    const __nv_bfloat16* __restrict__ Ah, const __nv_bfloat16* __restrict__ Al,
    const __nv_bfloat16* __restrict__ Bh, const __nv_bfloat16* __restrict__ Bl,
    const float* __restrict__ bias,
    __nv_bfloat16* __restrict__ Oh, __nv_bfloat16* __restrict__ Ol,
    __half* __restrict__ O16,
    int M, int N, int K, int mode)
{
    extern __shared__ __align__(16) unsigned short smem[];
    uint32_t ubase = (uint32_t)__cvta_generic_to_shared(smem);

    int tid  = threadIdx.x;
    int lane = tid & 31;
    int warp = tid >> 5;
    int warp_m = warp & 3;
    int warp_n = warp >> 2;
    int gid = lane >> 2;
    int tg  = lane & 3;

    int bm0 = blockIdx.x * GBM;
    int bn0 = blockIdx.y * GBN;

    int l = lane;
    uint32_t a_off = ((uint32_t)(warp_m * 32 + (l & 7) + ((l >> 3) & 1) * 8) * APITCH
                      + (l >> 4) * 8) * 2;
    uint32_t b_off = ((uint32_t)(warp_n * 64 + (l & 7) + (l >> 4) * 8) * APITCH
                      + ((l >> 3) & 1) * 8) * 2;

    float c[2][8][4];
    #pragma unroll
    for (int mt = 0; mt < 2; mt++)
        #pragma unroll
        for (int nt = 0; nt < 8; nt++)
            #pragma unroll
            for (int r = 0; r < 4; r++) c[mt][nt][r] = 0.f;

    auto prefetch = [&](int stage, int k0) {
        #pragma unroll
        for (int i = 0; i < 4; i++) {
            int idx = tid + i * 256;
            int arr = idx >> 9, rc = idx & 511;
            int row = rc >> 2, cc = rc & 3;
            const __nv_bfloat16* g = (arr ? Al : Ah)
                + (size_t)(bm0 + row) * K + k0 + cc * 8;
            uint32_t d = ubase + (uint32_t)((arr ? 2 * STG_HW : 0)
                + stage * STG_HW + row * APITCH + cc * 8) * 2;
            cp16(d, g, bm0 + row < M);
        }
        #pragma unroll
        for (int i = 0; i < 4; i++) {
            int idx = tid + i * 256;
            int arr = idx >> 9, rc = idx & 511;
            int row = rc >> 2, cc = rc & 3;
            const __nv_bfloat16* g = (arr ? Bl : Bh)
                + (size_t)(bn0 + row) * K + k0 + cc * 8;
            uint32_t d = ubase + (uint32_t)((arr ? 6 * STG_HW : 4 * STG_HW)
                + stage * STG_HW + row * APITCH + cc * 8) * 2;
            cp16(d, g, true);
        }
        asm volatile("cp.async.commit_group;");
    };

    int nk = K / GBK;
    prefetch(0, 0);

    for (int it = 0; it < nk; it++) {
        int cur = it & 1;
        if (it + 1 < nk) prefetch((it + 1) & 1, (it + 1) * GBK);
        if (it + 1 < nk) { asm volatile("cp.async.wait_group 1;"); }
        else             { asm volatile("cp.async.wait_group 0;"); }
        __syncthreads();

        uint32_t uAh = ubase + (uint32_t)(cur * STG_HW) * 2;
        uint32_t uAl = ubase + (uint32_t)(2 * STG_HW + cur * STG_HW) * 2;
        uint32_t uBh = ubase + (uint32_t)(4 * STG_HW + cur * STG_HW) * 2;
        uint32_t uBl = ubase + (uint32_t)(6 * STG_HW + cur * STG_HW) * 2;

        #pragma unroll
        for (int ks = 0; ks < 2; ks++) {
            uint32_t kb2 = ks * 32;
            uint32_t ah[2][4], al[2][4];
            LDSM4(ah[0], uAh + a_off + kb2);
            LDSM4(ah[1], uAh + a_off + kb2 + 16 * APITCH * 2);
            LDSM4(al[0], uAl + a_off + kb2);
            LDSM4(al[1], uAl + a_off + kb2 + 16 * APITCH * 2);
            #pragma unroll
            for (int ng = 0; ng < 4; ng++) {
                uint32_t bh[4], bl[4];
                uint32_t boff = b_off + (uint32_t)ng * (16 * APITCH * 2) + kb2;
                LDSM4(bh, uBh + boff);
                LDSM4(bl, uBl + boff);
                int n0 = 2 * ng, n1 = 2 * ng + 1;
                MMA_BF16(c[0][n0], ah[0], bh[0], bh[1]);
                MMA_BF16(c[1][n0], ah[1], bh[0], bh[1]);
                MMA_BF16(c[0][n1], ah[0], bh[2], bh[3]);
                MMA_BF16(c[1][n1], ah[1], bh[2], bh[3]);
                MMA_BF16(c[0][n0], al[0], bh[0], bh[1]);
                MMA_BF16(c[1][n0], al[1], bh[0], bh[1]);
                MMA_BF16(c[0][n1], al[0], bh[2], bh[3]);
                MMA_BF16(c[1][n1], al[1], bh[2], bh[3]);
                MMA_BF16(c[0][n0], ah[0], bl[0], bl[1]);
                MMA_BF16(c[1][n0], ah[1], bl[0], bl[1]);
                MMA_BF16(c[0][n1], ah[0], bl[2], bl[3]);
                MMA_BF16(c[1][n1], ah[1], bl[2], bl[3]);
            }
        }
        __syncthreads();
    }

    #pragma unroll
    for (int mt = 0; mt < 2; mt++) {
        int rbase = bm0 + warp_m * 32 + mt * 16 + gid;
        #pragma unroll
        for (int nt = 0; nt < 8; nt++) {
            int col = bn0 + warp_n * 64 + nt * 8 + 2 * tg;
            float v0 = c[mt][nt][0], v1 = c[mt][nt][1];
            float v2 = c[mt][nt][2], v3 = c[mt][nt][3];
            if (mode) {
                float bb0 = bias[col], bb1 = bias[col + 1];
                v0 = fmaxf(v0 + bb0, 0.f); v1 = fmaxf(v1 + bb1, 0.f);
                v2 = fmaxf(v2 + bb0, 0.f); v3 = fmaxf(v3 + bb1, 0.f);
                __nv_bfloat16 h0, l0, h1, l1;
                if (rbase < M) {
                    splitf(v0, h0, l0); splitf(v1, h1, l1);
                    *(uint32_t*)&Oh[(size_t)rbase * N + col] = pack2(h0, h1);
                    *(uint32_t*)&Ol[(size_t)rbase * N + col] = pack2(l0, l1);
                }
                if (rbase + 8 < M) {
                    splitf(v2, h0, l0); splitf(v3, h1, l1);
                    *(uint32_t*)&Oh[(size_t)(rbase + 8) * N + col] = pack2(h0, h1);
                    *(uint32_t*)&Ol[(size_t)(rbase + 8) * N + col] = pack2(l0, l1);
                }
            } else {
                if (rbase < M)
                    *(__half2*)&O16[(size_t)rbase * N + col] = __floats2half2_rn(v0, v1);
                if (rbase + 8 < M)
                    *(__half2*)&O16[(size_t)(rbase + 8) * N + col] = __floats2half2_rn(v2, v3);
            }
        }
    }
}

// ---------------- pooling (seg_ids sorted) ----------------------------------
#define POOL_ROWS 512
__global__ void __launch_bounds__(256) pool_kernel(const int* __restrict__ seg) {
    __shared__ int segs[POOL_ROWS];
    int r0 = blockIdx.x * POOL_ROWS;
    int nr = min(POOL_ROWS, NN - r0);
    if (nr <= 0) return;
    for (int r = threadIdx.x; r < nr; r += blockDim.x) segs[r] = seg[r0 + r];
    __syncthreads();
    int col = threadIdx.x;
    const float* h2 = (const float*)g_h2;
    float acc = 0.f;
    int cur = segs[0];
    for (int r = 0; r < nr; r++) {
        int s = segs[r];
        if (s != cur) { atomicAdd(&g_pool[cur * HID + col], acc); acc = 0.f; cur = s; }
        acc += h2[(size_t)(r0 + r) * HID + col];
    }
    atomicAdd(&g_pool[cur * HID + col], acc);
}

// ---------------- head: out = relu(g@Wd+bd) @ Wo + bo -----------------------
__global__ void __launch_bounds__(256) head_kernel(
    const float* __restrict__ Wd, const float* __restrict__ bd,
    const float* __restrict__ Wo, const float* __restrict__ bo,
    float* __restrict__ out)
{
    __shared__ float grow[HID];
    __shared__ float red[HID];
    int i = blockIdx.x, t = threadIdx.x;
    grow[t] = g_pool[i * HID + t];
    __syncthreads();
    float acc = bd[t];
    #pragma unroll 8
    for (int k = 0; k < HID; k++) acc += grow[k] * Wd[k * HID + t];
    acc = fmaxf(acc, 0.f);
    red[t] = acc * Wo[t];
    __syncthreads();
    for (int s = 128; s > 0; s >>= 1) {
        if (t < s) red[t] += red[t + s];
        __syncthreads();
    }
    if (t == 0) out[i] = red[0] + bo[0];
}

// ---------------- launch ----------------------------------------------------
extern "C" void kernel_launch(void* const* d_in, const int* in_sizes, int n_in,
                              void* d_out, int out_size)
{
    const float* x   = (const float*)d_in[0];
    const int*   esr = (const int*)  d_in[1];
    const int*   eds = (const int*)  d_in[2];
    const float* ew  = (const float*)d_in[3];
    const int*   seg = (const int*)  d_in[4];
    const float* W1  = (const float*)d_in[5];
    const float* b1  = (const float*)d_in[6];
    const float* W2  = (const float*)d_in[7];
    const float* b2  = (const float*)d_in[8];
    const float* Wd  = (const float*)d_in[9];
    const float* bd  = (const float*)d_in[10];
    const float* Wo  = (const float*)d_in[11];
    const float* bo  = (const float*)d_in[12];
    float* out = (float*)d_out;

    // idempotent, deterministic: no static guards (harness contract)
    cudaFuncSetAttribute(gemm_pipe_kernel,
                         cudaFuncAttributeMaxDynamicSharedMemorySize, GEMM_SMEM);

    void *p_axh, *p_axl, *p_h1h, *p_h1l, *p_t2h;
    void *p_W1th, *p_W1tl, *p_W2th, *p_W2tl;
    cudaGetSymbolAddress(&p_axh, g_axh);
    cudaGetSymbolAddress(&p_axl, g_axl);
    cudaGetSymbolAddress(&p_h1h, g_h1h);
    cudaGetSymbolAddress(&p_h1l, g_h1l);
    cudaGetSymbolAddress(&p_t2h, g_t2h);
    cudaGetSymbolAddress(&p_W1th, g_W1th);
    cudaGetSymbolAddress(&p_W1tl, g_W1tl);
    cudaGetSymbolAddress(&p_W2th, g_W2th);
    cudaGetSymbolAddress(&p_W2tl, g_W2tl);

    // 1) zero; x->fp16; weight transpose+split
    zero_kernel<<<(NN + 255) / 256, 256>>>();
    x2h_kernel<<<(NN * FIN / 4 + 255) / 256, 256>>>((const float4*)x);
    {
        dim3 g1(FIN / 32, HID / 32);
        transpose_split_kernel<<<g1, 256>>>(W1, (__nv_bfloat16*)p_W1th,
                                            (__nv_bfloat16*)p_W1tl, FIN, HID);
        dim3 g2(HID / 32, HID / 32);
        transpose_split_kernel<<<g2, 256>>>(W2, (__nv_bfloat16*)p_W2th,
                                            (__nv_bfloat16*)p_W2tl, HID, HID);
    }
    // 2) CSR build
    hist_kernel<<<(NE + 255) / 256, 256>>>(eds);
    scan_pre_kernel<<<NBLK, 256>>>();
    scan_mid_kernel<<<1, 256>>>();
    scan_post_kernel<<<NBLK, 256>>>();
    fill_kernel<<<(NE + 255) / 256, 256>>>(esr, eds, ew);
    // 3) spmm(x) -> (axh, axl)
    spmm128_kernel<<<NN / 8, 256>>>();
    // 4) h1 = relu(ax @ W1 + b1) -> (h1h, h1l)
    {
        dim3 grid((NN + GBM - 1) / GBM, HID / GBN);
        gemm_pipe_kernel<<<grid, 256, GEMM_SMEM>>>(
            (const __nv_bfloat16*)p_axh, (const __nv_bfloat16*)p_axl,
            (const __nv_bfloat16*)p_W1th, (const __nv_bfloat16*)p_W1tl,
            b1, (__nv_bfloat16*)p_h1h, (__nv_bfloat16*)p_h1l, nullptr,
            NN, HID, FIN, 1);
    }
    // 5) t2 = h1 @ W2 -> fp16
    {
        dim3 grid((NN + GBM - 1) / GBM, HID / GBN);
        gemm_pipe_kernel<<<grid, 256, GEMM_SMEM>>>(
            (const __nv_bfloat16*)p_h1h, (const __nv_bfloat16*)p_h1l,
            (const __nv_bfloat16*)p_W2th, (const __nv_bfloat16*)p_W2tl,
            b1 /*unused*/, nullptr, nullptr, (__half*)p_t2h,
            NN, HID, HID, 0);
    }
    // 6) h2 = relu(spmm(t2) + b2)
    spmm256_kernel<<<NN / 8, 256>>>(b2);
    // 7) pool
    pool_kernel<<<(NN + POOL_ROWS - 1) / POOL_ROWS, 256>>>(seg);
    // 8) head
    head_kernel<<<NG, HID>>>(Wd, bd, Wo, bo, out);
}